// round 5
// baseline (speedup 1.0000x reference)
#include <cuda_runtime.h>

#define NN 16384   // nodes
#define NE 4096    // edges
#define DD 256     // feature dim

// ---------------- scratch (device globals; no allocation allowed) ----------------
__device__ float g_xw1[NN * DD];   // x @ w1                       16 MB
__device__ float g_fe [NE * DD];   // edge features f = leaky(e^T @ xw1)   4 MB
__device__ float g_g  [NE * DD];   // g = f @ w2                    4 MB
__device__ float g_s1 [NN];        // exp(8*tanh(f_n/8)) node weight
__device__ float g_r  [NN];        // leaky(xw1) @ a22
__device__ float g_c  [NE];        // leaky(g) @ a21

__device__ __forceinline__ float lrelu(float v) { return v > 0.0f ? v : 0.1f * v; }

// exp(8*tanh(z/8)) using tanh(y) = 1 - 2/(e^{2y}+1) (exact identity, safe at +-inf)
__device__ __forceinline__ float softexp8(float z) {
    float v = __expf(z * 0.25f);                 // e^{2*(z/8)}
    float t = 1.0f - __fdividef(2.0f, v + 1.0f); // tanh(z/8); v=inf -> t=1, v=0 -> t=-1
    return __expf(8.0f * t);
}

// =====================================================================
// Generic [M,256] @ [256,256] GEMM, 32x128 tile, 128 threads, 4x8 micro
// sel==0: C = g_xw1, A = param     (xw1 = x @ w1)
// sel==1: C = g_g,   A = g_fe     (g = f_edge @ w2)
// =====================================================================
__global__ void __launch_bounds__(128) k_mm(const float* __restrict__ Ain,
                                            const float* __restrict__ B,
                                            int sel) {
    __shared__ float As[32][33];
    __shared__ float Bs[32][132];
    const float* A = sel ? g_fe : Ain;
    float*       C = sel ? g_g  : g_xw1;

    const int tid = threadIdx.x;
    const int la = tid & 31, wg = tid >> 5;   // load mapping
    const int tx = tid & 15, ty = tid >> 4;   // compute mapping
    const int r0 = ty * 4, c0 = tx * 8;
    const int m0 = blockIdx.x * 32;
    const int dbase = blockIdx.y * 128;

    float acc[4][8];
#pragma unroll
    for (int i = 0; i < 4; i++)
#pragma unroll
        for (int j = 0; j < 8; j++) acc[i][j] = 0.0f;

    float ra[8]; float4 rb[8];

    auto load = [&](int kb) {
#pragma unroll
        for (int j = 0; j < 8; j++)
            ra[j] = A[(size_t)(m0 + wg + 4 * j) * DD + kb + la];
#pragma unroll
        for (int j = 0; j < 8; j++)
            rb[j] = *reinterpret_cast<const float4*>(
                &B[(size_t)(kb + wg + 4 * j) * DD + dbase + la * 4]);
    };
    auto store = [&]() {
#pragma unroll
        for (int j = 0; j < 8; j++) As[wg + 4 * j][la] = ra[j];
#pragma unroll
        for (int j = 0; j < 8; j++)
            *reinterpret_cast<float4*>(&Bs[wg + 4 * j][la * 4]) = rb[j];
    };

    load(0); store(); __syncthreads();
    const int KT = DD / 32;
    for (int kt = 0; kt < KT; kt++) {
        if (kt + 1 < KT) load((kt + 1) * 32);
#pragma unroll 8
        for (int k = 0; k < 32; k++) {
            float a[4];
#pragma unroll
            for (int i = 0; i < 4; i++) a[i] = As[r0 + i][k];
            float4 b0 = *reinterpret_cast<const float4*>(&Bs[k][c0]);
            float4 b1 = *reinterpret_cast<const float4*>(&Bs[k][c0 + 4]);
            float b[8] = {b0.x, b0.y, b0.z, b0.w, b1.x, b1.y, b1.z, b1.w};
#pragma unroll
            for (int i = 0; i < 4; i++)
#pragma unroll
                for (int j = 0; j < 8; j++) acc[i][j] += a[i] * b[j];
        }
        __syncthreads();
        if (kt + 1 < KT) { store(); __syncthreads(); }
    }
#pragma unroll
    for (int i = 0; i < 4; i++) {
        float* o = &C[(size_t)(m0 + r0 + i) * DD + dbase + c0];
        *reinterpret_cast<float4*>(o)     = make_float4(acc[i][0], acc[i][1], acc[i][2], acc[i][3]);
        *reinterpret_cast<float4*>(o + 4) = make_float4(acc[i][4], acc[i][5], acc[i][6], acc[i][7]);
    }
}

// =====================================================================
// Per-node: f = leaky(xw1)@a1, r = leaky(xw1)@a22, s1 = exp(8 tanh(f/8))
// one warp per row
// =====================================================================
__global__ void k_node(const float* __restrict__ a1, const float* __restrict__ a22) {
    const int lane = threadIdx.x & 31;
    const int row = blockIdx.x * 8 + (threadIdx.x >> 5);
    const float* rp = &g_xw1[(size_t)row * DD];
    float f = 0.0f, r = 0.0f;
#pragma unroll
    for (int j = 0; j < 8; j++) {
        int d = lane + 32 * j;
        float v = lrelu(rp[d]);
        f += v * __ldg(&a1[d]);
        r += v * __ldg(&a22[d]);
    }
#pragma unroll
    for (int o = 16; o > 0; o >>= 1) {
        f += __shfl_down_sync(0xffffffffu, f, o);
        r += __shfl_down_sync(0xffffffffu, r, o);
    }
    if (lane == 0) { g_s1[row] = softexp8(f); g_r[row] = r; }
}

// =====================================================================
// Per-edge: c = leaky(g)@a21, one warp per row
// =====================================================================
__global__ void k_cedge(const float* __restrict__ a21) {
    const int lane = threadIdx.x & 31;
    const int row = blockIdx.x * 8 + (threadIdx.x >> 5);
    const float* rp = &g_g[(size_t)row * DD];
    float c = 0.0f;
#pragma unroll
    for (int j = 0; j < 8; j++) {
        int d = lane + 32 * j;
        c += lrelu(rp[d]) * __ldg(&a21[d]);
    }
#pragma unroll
    for (int o = 16; o > 0; o >>= 1) c += __shfl_down_sync(0xffffffffu, c, o);
    if (lane == 0) g_c[row] = c;
}

// =====================================================================
// Big GEMM 1 (fused): G[e,d] = sum_n (H[n,e]*s1[n]) * xw1[n,d]
//                     colsum[e] = sum_n H[n,e]*s1[n]
//                     g_fe = leaky(G / colsum)
// tiles: 32 edges x 128 d, K over N (512 tiles)
// =====================================================================
__global__ void __launch_bounds__(128) k_edge(const float* __restrict__ H) {
    __shared__ float As[32][33];   // As[e_local][n_local] (transposed, pre-scaled)
    __shared__ float Bs[32][132];  // Bs[n_local][d]
    const int tid = threadIdx.x;
    const int la = tid & 31, wg = tid >> 5;
    const int tx = tid & 15, ty = tid >> 4;
    const int r0 = ty * 4, c0 = tx * 8;
    const int e0 = blockIdx.x * 32;
    const int dbase = blockIdx.y * 128;

    float acc[4][8];
#pragma unroll
    for (int i = 0; i < 4; i++)
#pragma unroll
        for (int j = 0; j < 8; j++) acc[i][j] = 0.0f;
    float cs[4] = {0.0f, 0.0f, 0.0f, 0.0f};

    float ra[8], rs1[8]; float4 rb[8];

    auto load = [&](int n0) {
#pragma unroll
        for (int j = 0; j < 8; j++) {
            int n = n0 + wg + 4 * j;
            ra[j]  = H[(size_t)n * NE + e0 + la];
            rs1[j] = __ldg(&g_s1[n]);
            rb[j]  = *reinterpret_cast<const float4*>(
                &g_xw1[(size_t)n * DD + dbase + la * 4]);
        }
    };
    auto store = [&]() {
#pragma unroll
        for (int j = 0; j < 8; j++) As[la][wg + 4 * j] = ra[j] * rs1[j];
#pragma unroll
        for (int j = 0; j < 8; j++)
            *reinterpret_cast<float4*>(&Bs[wg + 4 * j][la * 4]) = rb[j];
    };

    load(0); store(); __syncthreads();
    const int KT = NN / 32;
    for (int kt = 0; kt < KT; kt++) {
        if (kt + 1 < KT) load((kt + 1) * 32);
#pragma unroll 8
        for (int k = 0; k < 32; k++) {
            float a[4];
#pragma unroll
            for (int i = 0; i < 4; i++) { a[i] = As[r0 + i][k]; cs[i] += a[i]; }
            float4 b0 = *reinterpret_cast<const float4*>(&Bs[k][c0]);
            float4 b1 = *reinterpret_cast<const float4*>(&Bs[k][c0 + 4]);
            float b[8] = {b0.x, b0.y, b0.z, b0.w, b1.x, b1.y, b1.z, b1.w};
#pragma unroll
            for (int i = 0; i < 4; i++)
#pragma unroll
                for (int j = 0; j < 8; j++) acc[i][j] += a[i] * b[j];
        }
        __syncthreads();
        if (kt + 1 < KT) { store(); __syncthreads(); }
    }
#pragma unroll
    for (int i = 0; i < 4; i++) {
        float inv = 1.0f / cs[i];
        float* o = &g_fe[(size_t)(e0 + r0 + i) * DD + dbase + c0];
        float4 v0 = make_float4(lrelu(acc[i][0] * inv), lrelu(acc[i][1] * inv),
                                lrelu(acc[i][2] * inv), lrelu(acc[i][3] * inv));
        float4 v1 = make_float4(lrelu(acc[i][4] * inv), lrelu(acc[i][5] * inv),
                                lrelu(acc[i][6] * inv), lrelu(acc[i][7] * inv));
        *reinterpret_cast<float4*>(o)     = v0;
        *reinterpret_cast<float4*>(o + 4) = v1;
    }
}

// =====================================================================
// Big GEMM 2 (fused): w(n,e) = H[n,e]*exp(8 tanh((c_e + r_n)/8))
//                     out[n,d] = leaky( (sum_e w*g[e,d]) / (sum_e w) )
// tiles: 32 nodes x 128 d, K over E (128 tiles)
// =====================================================================
__global__ void __launch_bounds__(128) k_out(const float* __restrict__ H,
                                             float* __restrict__ out) {
    __shared__ float As[32][33];   // As[n_local][e_local] = H * s2
    __shared__ float Bs[32][132];  // Bs[e_local][d] = g
    __shared__ float rsh[32];
    const int tid = threadIdx.x;
    const int la = tid & 31, wg = tid >> 5;
    const int tx = tid & 15, ty = tid >> 4;
    const int r0 = ty * 4, c0 = tx * 8;
    const int m0 = blockIdx.x * 32;
    const int dbase = blockIdx.y * 128;

    if (tid < 32) rsh[tid] = g_r[m0 + tid];

    float acc[4][8];
#pragma unroll
    for (int i = 0; i < 4; i++)
#pragma unroll
        for (int j = 0; j < 8; j++) acc[i][j] = 0.0f;
    float rs[4] = {0.0f, 0.0f, 0.0f, 0.0f};

    float ra[8]; float4 rb[8]; float cv = 0.0f;

    auto load = [&](int e0) {
        cv = __ldg(&g_c[e0 + la]);   // each thread touches a single edge column
#pragma unroll
        for (int j = 0; j < 8; j++)
            ra[j] = H[(size_t)(m0 + wg + 4 * j) * NE + e0 + la];
#pragma unroll
        for (int j = 0; j < 8; j++)
            rb[j] = *reinterpret_cast<const float4*>(
                &g_g[(size_t)(e0 + wg + 4 * j) * DD + dbase + la * 4]);
    };
    auto store = [&]() {
#pragma unroll
        for (int j = 0; j < 8; j++) {
            float av = 0.0f;
            if (ra[j] != 0.0f) av = softexp8(cv + rsh[wg + 4 * j]);  // H is 0/1
            As[wg + 4 * j][la] = av;
        }
#pragma unroll
        for (int j = 0; j < 8; j++)
            *reinterpret_cast<float4*>(&Bs[wg + 4 * j][la * 4]) = rb[j];
    };

    load(0);
    __syncthreads();   // rsh visible before store() reads it
    store(); __syncthreads();
    const int KT = NE / 32;
    for (int kt = 0; kt < KT; kt++) {
        if (kt + 1 < KT) load((kt + 1) * 32);
#pragma unroll 8
        for (int k = 0; k < 32; k++) {
            float a[4];
#pragma unroll
            for (int i = 0; i < 4; i++) { a[i] = As[r0 + i][k]; rs[i] += a[i]; }
            float4 b0 = *reinterpret_cast<const float4*>(&Bs[k][c0]);
            float4 b1 = *reinterpret_cast<const float4*>(&Bs[k][c0 + 4]);
            float b[8] = {b0.x, b0.y, b0.z, b0.w, b1.x, b1.y, b1.z, b1.w};
#pragma unroll
            for (int i = 0; i < 4; i++)
#pragma unroll
                for (int j = 0; j < 8; j++) acc[i][j] += a[i] * b[j];
        }
        __syncthreads();
        if (kt + 1 < KT) { store(); __syncthreads(); }
    }
#pragma unroll
    for (int i = 0; i < 4; i++) {
        float inv = 1.0f / rs[i];
        float* o = &out[(size_t)(m0 + r0 + i) * DD + dbase + c0];
        float4 v0 = make_float4(lrelu(acc[i][0] * inv), lrelu(acc[i][1] * inv),
                                lrelu(acc[i][2] * inv), lrelu(acc[i][3] * inv));
        float4 v1 = make_float4(lrelu(acc[i][4] * inv), lrelu(acc[i][5] * inv),
                                lrelu(acc[i][6] * inv), lrelu(acc[i][7] * inv));
        *reinterpret_cast<float4*>(o)     = v0;
        *reinterpret_cast<float4*>(o + 4) = v1;
    }
}

// =====================================================================
extern "C" void kernel_launch(void* const* d_in, const int* in_sizes, int n_in,
                              void* d_out, int out_size) {
    const float* x   = (const float*)d_in[0];   // [N, 256]
    const float* H   = (const float*)d_in[1];   // [N, E]
    const float* w1  = (const float*)d_in[2];   // [256, 256]
    const float* w2  = (const float*)d_in[3];   // [256, 256]
    const float* a1  = (const float*)d_in[4];   // [256]
    const float* a21 = (const float*)d_in[5];   // [256]
    const float* a22 = (const float*)d_in[6];   // [256]
    float* out = (float*)d_out;                 // [N, 256]

    // 1) xw1 = x @ w1
    k_mm<<<dim3(NN / 32, 2), 128>>>(x, w1, 0);
    // 2) per-node stats: s1, r
    k_node<<<NN / 8, 256>>>(a1, a22);
    // 3) edge features: f_edge = leaky((H*s1)^T @ xw1 / colsum)
    k_edge<<<dim3(NE / 32, 2), 128>>>(H);
    // 4) g = f_edge @ w2
    k_mm<<<dim3(NE / 32, 2), 128>>>(nullptr, w2, 1);
    // 5) per-edge stats: c
    k_cedge<<<NE / 8, 256>>>(a21);
    // 6) out = leaky(normalize(H*s2) @ g)
    k_out<<<dim3(NN / 32, 2), 128>>>(H, out);
}

// round 7
// speedup vs baseline: 3.3358x; 3.3358x over previous
#include <cuda_runtime.h>
#include <cstdint>

#define NN 16384
#define NE 4096
#define DD 256
#define KS 4             // k-splits for gemm1
#define NCH (NN / KS)    // 4096 nodes per split

// ---------------- scratch (device globals; no allocation allowed) ----------------
__device__ float g_xw1 [NN * DD];
__device__ float g_xw1T[DD * NN];
__device__ float g_fe  [NE * DD];
__device__ float g_g   [NE * DD];
__device__ float g_gT  [DD * NE];
__device__ float g_s1  [NN];
__device__ float g_r   [NN];
__device__ float g_c   [NE];
__device__ float g_p1  [KS * NE * DD];   // gemm1 k-split partials (64 MB)
__device__ float g_pcs [KS * NE];        // gemm1 colsum partials

__device__ __forceinline__ float lrelu(float v) { return v > 0.0f ? v : 0.1f * v; }

// exp(8*tanh(z/8)) via tanh(y) = 1 - 2/(e^{2y}+1) (exact, safe at +-inf)
__device__ __forceinline__ float softexp8(float z) {
    float v = __expf(z * 0.25f);
    float t = 1.0f - __fdividef(2.0f, v + 1.0f);
    return __expf(8.0f * t);
}

__device__ __forceinline__ uint32_t tf32c(float x) {
    uint32_t r; asm("cvt.rna.tf32.f32 %0, %1;" : "=r"(r) : "f"(x)); return r;
}

__device__ __forceinline__ void mma8(float* d, const uint32_t a[4],
                                     uint32_t b0, uint32_t b1) {
    asm volatile(
        "mma.sync.aligned.m16n8k8.row.col.f32.tf32.tf32.f32 "
        "{%0,%1,%2,%3}, {%4,%5,%6,%7}, {%8,%9}, {%0,%1,%2,%3};"
        : "+f"(d[0]), "+f"(d[1]), "+f"(d[2]), "+f"(d[3])
        : "r"(a[0]), "r"(a[1]), "r"(a[2]), "r"(a[3]), "r"(b0), "r"(b1));
}

#define PAD 36
#define A_STRIDE (128 * PAD)   // u32 per A buffer (4608)
#define B_STRIDE (256 * PAD)   // u32 per B buffer (9216)
#define SM_U32 (2 * A_STRIDE + 2 * B_STRIDE + 512)
#define SMEMB (SM_U32 * 4)     // 112640 bytes

// warp-tile MMA over one 32-K stage: CTA tile 128x256, warp tile 32x64
__device__ __forceinline__ void mma_stage(const uint32_t* __restrict__ As,
                                          const uint32_t* __restrict__ Bs,
                                          float acc[2][8][4],
                                          int lane, int wm, int wn) {
    const int qr = lane >> 2, qc = lane & 3;
#pragma unroll
    for (int ks = 0; ks < 4; ks++) {
        const int kk = ks * 8;
        uint32_t af[2][4];
#pragma unroll
        for (int mt = 0; mt < 2; mt++) {
            const uint32_t* ap = As + (wm * 32 + mt * 16 + qr) * PAD + kk + qc;
            af[mt][0] = ap[0];
            af[mt][1] = ap[8 * PAD];
            af[mt][2] = ap[4];
            af[mt][3] = ap[8 * PAD + 4];
        }
#pragma unroll
        for (int nt = 0; nt < 8; nt++) {
            const uint32_t* bp = Bs + (wn * 64 + nt * 8 + qr) * PAD + kk + qc;
            uint32_t b0 = bp[0], b1 = bp[4];
#pragma unroll
            for (int mt = 0; mt < 2; mt++)
                mma8(acc[mt][nt], af[mt], b0, b1);
        }
    }
}

// ---------------- SIMT [M,256]@[256,256] (x@w1 and f@w2) ----------------
__global__ void __launch_bounds__(128) k_mm(const float* __restrict__ Ain,
                                            const float* __restrict__ B, int sel) {
    __shared__ float As[32][33];
    __shared__ float Bs[32][132];
    const float* A = sel ? g_fe : Ain;
    float*       C = sel ? g_g  : g_xw1;
    const int tid = threadIdx.x;
    const int la = tid & 31, wg = tid >> 5;
    const int tx = tid & 15, ty = tid >> 4;
    const int r0 = ty * 4, c0 = tx * 8;
    const int m0 = blockIdx.x * 32;
    const int dbase = blockIdx.y * 128;

    float acc[4][8];
#pragma unroll
    for (int i = 0; i < 4; i++)
#pragma unroll
        for (int j = 0; j < 8; j++) acc[i][j] = 0.0f;
    float ra[8]; float4 rb[8];
    auto load = [&](int kb) {
#pragma unroll
        for (int j = 0; j < 8; j++)
            ra[j] = A[(size_t)(m0 + wg + 4 * j) * DD + kb + la];
#pragma unroll
        for (int j = 0; j < 8; j++)
            rb[j] = *reinterpret_cast<const float4*>(
                &B[(size_t)(kb + wg + 4 * j) * DD + dbase + la * 4]);
    };
    auto store = [&]() {
#pragma unroll
        for (int j = 0; j < 8; j++) As[wg + 4 * j][la] = ra[j];
#pragma unroll
        for (int j = 0; j < 8; j++)
            *reinterpret_cast<float4*>(&Bs[wg + 4 * j][la * 4]) = rb[j];
    };
    load(0); store(); __syncthreads();
    for (int kt = 0; kt < DD / 32; kt++) {
        if (kt + 1 < DD / 32) load((kt + 1) * 32);
#pragma unroll 8
        for (int k = 0; k < 32; k++) {
            float a[4];
#pragma unroll
            for (int i = 0; i < 4; i++) a[i] = As[r0 + i][k];
            float4 b0 = *reinterpret_cast<const float4*>(&Bs[k][c0]);
            float4 b1 = *reinterpret_cast<const float4*>(&Bs[k][c0 + 4]);
            float b[8] = {b0.x, b0.y, b0.z, b0.w, b1.x, b1.y, b1.z, b1.w};
#pragma unroll
            for (int i = 0; i < 4; i++)
#pragma unroll
                for (int j = 0; j < 8; j++) acc[i][j] += a[i] * b[j];
        }
        __syncthreads();
        if (kt + 1 < DD / 32) { store(); __syncthreads(); }
    }
#pragma unroll
    for (int i = 0; i < 4; i++) {
        float* o = &C[(size_t)(m0 + r0 + i) * DD + dbase + c0];
        *reinterpret_cast<float4*>(o)     = make_float4(acc[i][0], acc[i][1], acc[i][2], acc[i][3]);
        *reinterpret_cast<float4*>(o + 4) = make_float4(acc[i][4], acc[i][5], acc[i][6], acc[i][7]);
    }
}

__global__ void k_node(const float* __restrict__ a1, const float* __restrict__ a22) {
    const int lane = threadIdx.x & 31;
    const int row = blockIdx.x * 8 + (threadIdx.x >> 5);
    const float* rp = &g_xw1[(size_t)row * DD];
    float f = 0.0f, r = 0.0f;
#pragma unroll
    for (int j = 0; j < 8; j++) {
        int d = lane + 32 * j;
        float v = lrelu(rp[d]);
        f += v * __ldg(&a1[d]);
        r += v * __ldg(&a22[d]);
    }
#pragma unroll
    for (int o = 16; o > 0; o >>= 1) {
        f += __shfl_down_sync(0xffffffffu, f, o);
        r += __shfl_down_sync(0xffffffffu, r, o);
    }
    if (lane == 0) { g_s1[row] = softexp8(f); g_r[row] = r; }
}

__global__ void k_cedge(const float* __restrict__ a21) {
    const int lane = threadIdx.x & 31;
    const int row = blockIdx.x * 8 + (threadIdx.x >> 5);
    const float* rp = &g_g[(size_t)row * DD];
    float c = 0.0f;
#pragma unroll
    for (int j = 0; j < 8; j++) {
        int d = lane + 32 * j;
        c += lrelu(rp[d]) * __ldg(&a21[d]);
    }
#pragma unroll
    for (int o = 16; o > 0; o >>= 1) c += __shfl_down_sync(0xffffffffu, c, o);
    if (lane == 0) g_c[row] = c;
}

// transpose: 0: xw1[NN,DD]->xw1T[DD,NN]; 1: g[NE,DD]->gT[DD,NE]
__global__ void k_tr(int which) {
    __shared__ float t[32][33];
    const float* s = which ? g_g  : g_xw1;
    float*       d = which ? g_gT : g_xw1T;
    const int R = which ? NE : NN;
    const int c0 = blockIdx.x * 32, r0 = blockIdx.y * 32;
    const int x = threadIdx.x, y = threadIdx.y;
#pragma unroll
    for (int j = 0; j < 32; j += 8)
        t[y + j][x] = s[(size_t)(r0 + y + j) * DD + c0 + x];
    __syncthreads();
#pragma unroll
    for (int j = 0; j < 32; j += 8)
        d[(size_t)(c0 + y + j) * R + r0 + x] = t[x][y + j];
}

// ---------------- GEMM1 (mma.sync tf32, k-split partials) ----------------
// partial[s][e,d] = sum_{n in split s} (H[n,e]*s1[n]) * xw1[n,d]
// pcs[s][e]      = sum_{n in split s} H[n,e]*s1[n]
__global__ void __launch_bounds__(512, 1) k_gemm1(const float* __restrict__ H) {
    extern __shared__ uint32_t smu[];
    uint32_t* Ab = smu;
    uint32_t* Bb = smu + 2 * A_STRIDE;
    float* red = (float*)(smu + 2 * A_STRIDE + 2 * B_STRIDE);

    const int tid = threadIdx.x;
    const int lane = tid & 31;
    const int wid = tid >> 5;
    const int wm = wid >> 2, wn = wid & 3;
    const int e0 = blockIdx.x * 128;
    const int s  = blockIdx.y;
    const int ns = s * NCH;

    const int et = tid & 127, nq = tid >> 7;   // A fill: e column, n-quad
    const int dt = tid >> 1,  bh = tid & 1;    // B fill: d row, half

    float acc[2][8][4];
#pragma unroll
    for (int mt = 0; mt < 2; mt++)
#pragma unroll
        for (int nt = 0; nt < 8; nt++)
#pragma unroll
            for (int q = 0; q < 4; q++) acc[mt][nt][q] = 0.0f;
    float cacc = 0.0f;

    uint32_t av[8], bv[16];
    auto loadA = [&](int n0) {
#pragma unroll
        for (int i = 0; i < 8; i++) {
            const int n = n0 + nq * 8 + i;
            float hv = H[(size_t)n * NE + e0 + et] * __ldg(&g_s1[n]);
            cacc += hv;
            av[i] = tf32c(hv);
        }
    };
    auto loadB = [&](int n0) {
#pragma unroll
        for (int j = 0; j < 4; j++) {
            float4 v = *(const float4*)&g_xw1T[(size_t)dt * NN + n0 + bh * 16 + j * 4];
            bv[j * 4 + 0] = tf32c(v.x); bv[j * 4 + 1] = tf32c(v.y);
            bv[j * 4 + 2] = tf32c(v.z); bv[j * 4 + 3] = tf32c(v.w);
        }
    };
    auto storeAB = [&](int b) {
        uint32_t* As = Ab + b * A_STRIDE;
        *(uint4*)&As[et * PAD + nq * 8]     = make_uint4(av[0], av[1], av[2], av[3]);
        *(uint4*)&As[et * PAD + nq * 8 + 4] = make_uint4(av[4], av[5], av[6], av[7]);
        uint32_t* Bs = Bb + b * B_STRIDE;
#pragma unroll
        for (int j = 0; j < 4; j++)
            *(uint4*)&Bs[dt * PAD + bh * 16 + j * 4] =
                make_uint4(bv[j * 4], bv[j * 4 + 1], bv[j * 4 + 2], bv[j * 4 + 3]);
    };

    loadA(ns); loadB(ns); storeAB(0); __syncthreads();
    const int T = NCH / 32;
    for (int t = 0; t < T; t++) {
        const int b = t & 1;
        if (t + 1 < T) { loadA(ns + (t + 1) * 32); loadB(ns + (t + 1) * 32); }
        mma_stage(Ab + b * A_STRIDE, Bb + b * B_STRIDE, acc, lane, wm, wn);
        if (t + 1 < T) storeAB(b ^ 1);
        __syncthreads();
    }

    red[nq * 128 + et] = cacc;
    __syncthreads();
    if (tid < 128)
        g_pcs[s * NE + e0 + tid] =
            red[tid] + red[128 + tid] + red[256 + tid] + red[384 + tid];

    const int qr = lane >> 2, qc2 = (lane & 3) * 2;
    float* base = g_p1 + (size_t)s * NE * DD;
#pragma unroll
    for (int mt = 0; mt < 2; mt++) {
        const int r = e0 + wm * 32 + mt * 16 + qr;
#pragma unroll
        for (int nt = 0; nt < 8; nt++) {
            const int c = wn * 64 + nt * 8 + qc2;
            *(float2*)&base[(size_t)r * DD + c] =
                make_float2(acc[mt][nt][0], acc[mt][nt][1]);
            *(float2*)&base[(size_t)(r + 8) * DD + c] =
                make_float2(acc[mt][nt][2], acc[mt][nt][3]);
        }
    }
}

// gemm1 reduction: g_fe = lrelu( (sum_s p1) / (sum_s pcs) )
__global__ void k_red1() {
    const int idx = blockIdx.x * 256 + threadIdx.x;    // float4 index over [NE][64]
    const int e = idx >> 6;
    float cs = g_pcs[e] + g_pcs[NE + e] + g_pcs[2 * NE + e] + g_pcs[3 * NE + e];
    float inv = 1.0f / cs;
    const float4* p = (const float4*)g_p1;
    const int SP = NE * (DD / 4);
    float4 v0 = p[idx], v1 = p[idx + SP], v2 = p[idx + 2 * SP], v3 = p[idx + 3 * SP];
    float4 o;
    o.x = lrelu((v0.x + v1.x + v2.x + v3.x) * inv);
    o.y = lrelu((v0.y + v1.y + v2.y + v3.y) * inv);
    o.z = lrelu((v0.z + v1.z + v2.z + v3.z) * inv);
    o.w = lrelu((v0.w + v1.w + v2.w + v3.w) * inv);
    ((float4*)g_fe)[idx] = o;
}

// ---------------- GEMM2 (mma.sync tf32, fused softmax + epilogue) ----------------
// w[n,e] = H[n,e]*softexp8(c_e + r_n); out[n,d] = lrelu((W@g)/rowsum)
__global__ void __launch_bounds__(512, 1) k_gemm2(const float* __restrict__ H,
                                                  float* __restrict__ out) {
    extern __shared__ uint32_t smu[];
    uint32_t* Ab = smu;
    uint32_t* Bb = smu + 2 * A_STRIDE;
    float* red = (float*)(smu + 2 * A_STRIDE + 2 * B_STRIDE);
    float* rsh  = red;        // [128] r values
    float* rsum = red + 128;  // [128] row sums

    const int tid = threadIdx.x;
    const int lane = tid & 31;
    const int wid = tid >> 5;
    const int wm = wid >> 2, wn = wid & 3;
    const int n00 = blockIdx.x * 128;

    const int el = tid & 31;                 // A fill: e-local column (lane)
    const int dt = tid >> 1, bh = tid & 1;   // B fill

    if (tid < 128) rsh[tid] = g_r[n00 + tid];
    __syncthreads();

    float acc[2][8][4];
#pragma unroll
    for (int mt = 0; mt < 2; mt++)
#pragma unroll
        for (int nt = 0; nt < 8; nt++)
#pragma unroll
            for (int q = 0; q < 4; q++) acc[mt][nt][q] = 0.0f;
    float racc[8];
#pragma unroll
    for (int i = 0; i < 8; i++) racc[i] = 0.0f;

    uint32_t av[8], bv[16];
    auto loadA = [&](int e0) {
        const float cvl = __ldg(&g_c[e0 + el]);
#pragma unroll
        for (int i = 0; i < 8; i++) {
            const int nl = wid * 8 + i;
            float h = H[(size_t)(n00 + nl) * NE + e0 + el];
            float w = 0.0f;
            if (h != 0.0f) w = softexp8(cvl + rsh[nl]);
            racc[i] += w;
            av[i] = tf32c(w);
        }
    };
    auto loadB = [&](int e0) {
#pragma unroll
        for (int j = 0; j < 4; j++) {
            float4 v = *(const float4*)&g_gT[(size_t)dt * NE + e0 + bh * 16 + j * 4];
            bv[j * 4 + 0] = tf32c(v.x); bv[j * 4 + 1] = tf32c(v.y);
            bv[j * 4 + 2] = tf32c(v.z); bv[j * 4 + 3] = tf32c(v.w);
        }
    };
    auto storeAB = [&](int b) {
        uint32_t* As = Ab + b * A_STRIDE;
#pragma unroll
        for (int i = 0; i < 8; i++)
            As[(wid * 8 + i) * PAD + el] = av[i];
        uint32_t* Bs = Bb + b * B_STRIDE;
#pragma unroll
        for (int j = 0; j < 4; j++)
            *(uint4*)&Bs[dt * PAD + bh * 16 + j * 4] =
                make_uint4(bv[j * 4], bv[j * 4 + 1], bv[j * 4 + 2], bv[j * 4 + 3]);
    };

    loadA(0); loadB(0); storeAB(0); __syncthreads();
    const int T = NE / 32;
    for (int t = 0; t < T; t++) {
        const int b = t & 1;
        if (t + 1 < T) { loadA((t + 1) * 32); loadB((t + 1) * 32); }
        mma_stage(Ab + b * A_STRIDE, Bb + b * B_STRIDE, acc, lane, wm, wn);
        if (t + 1 < T) storeAB(b ^ 1);
        __syncthreads();
    }

    // rowsum: reduce racc over the 32 lanes (e-columns) of each warp
#pragma unroll
    for (int i = 0; i < 8; i++) {
        float v = racc[i];
#pragma unroll
        for (int o = 16; o > 0; o >>= 1) v += __shfl_xor_sync(0xffffffffu, v, o);
        if (lane == 0) rsum[wid * 8 + i] = v;
    }
    __syncthreads();

    const int qr = lane >> 2, qc2 = (lane & 3) * 2;
#pragma unroll
    for (int mt = 0; mt < 2; mt++) {
        const int rl = wm * 32 + mt * 16 + qr;
        const float inv0 = 1.0f / rsum[rl];
        const float inv1 = 1.0f / rsum[rl + 8];
#pragma unroll
        for (int nt = 0; nt < 8; nt++) {
            const int c = wn * 64 + nt * 8 + qc2;
            *(float2*)&out[(size_t)(n00 + rl) * DD + c] =
                make_float2(lrelu(acc[mt][nt][0] * inv0), lrelu(acc[mt][nt][1] * inv0));
            *(float2*)&out[(size_t)(n00 + rl + 8) * DD + c] =
                make_float2(lrelu(acc[mt][nt][2] * inv1), lrelu(acc[mt][nt][3] * inv1));
        }
    }
}

// =====================================================================
extern "C" void kernel_launch(void* const* d_in, const int* in_sizes, int n_in,
                              void* d_out, int out_size) {
    const float* x   = (const float*)d_in[0];
    const float* H   = (const float*)d_in[1];
    const float* w1  = (const float*)d_in[2];
    const float* w2  = (const float*)d_in[3];
    const float* a1  = (const float*)d_in[4];
    const float* a21 = (const float*)d_in[5];
    const float* a22 = (const float*)d_in[6];
    float* out = (float*)d_out;

    cudaFuncSetAttribute(k_gemm1, cudaFuncAttributeMaxDynamicSharedMemorySize, SMEMB);
    cudaFuncSetAttribute(k_gemm2, cudaFuncAttributeMaxDynamicSharedMemorySize, SMEMB);

    k_mm<<<dim3(NN / 32, 2), 128>>>(x, w1, 0);
    k_node<<<NN / 8, 256>>>(a1, a22);
    k_tr<<<dim3(DD / 32, NN / 32), dim3(32, 8)>>>(0);
    k_gemm1<<<dim3(NE / 128, KS), 512, SMEMB>>>(H);
    k_red1<<<NE * (DD / 4) / 256, 256>>>();
    k_mm<<<dim3(NE / 32, 2), 128>>>(nullptr, w2, 1);
    k_cedge<<<NE / 8, 256>>>(a21);
    k_tr<<<dim3(DD / 32, NE / 32), dim3(32, 8)>>>(1);
    k_gemm2<<<NN / 128, 512, SMEMB>>>(H, out);
}